// round 3
// baseline (speedup 1.0000x reference)
#include <cuda_runtime.h>
#include <cuda_bf16.h>
#include <cstdint>

// ---------------------------------------------------------------------------
// Problem constants
// ---------------------------------------------------------------------------
#define BATCH   4
#define SEQ     4096
#define HIDDEN  1024
#define MTOT    (BATCH * SEQ)          // 16384
#define NTOT    (3 * HIDDEN)           // 3072 (S | out1 | out2)

// GEMM tiling
#define BM 128
#define BN 128
#define BK 64                           // 64 bf16 = 128 B row (SW128 swizzle)
#define NSTAGE 3
#define NKT (3 * (HIDDEN / BK))         // 3 split-products x 16 k-tiles = 48

#define STAGE_BYTES 32768               // A 16KB + B 16KB
#define SMEM_TOTAL  (NSTAGE * STAGE_BYTES)

// Scan tiling
#define NCH   64
#define CHUNK 64

// ---------------------------------------------------------------------------
// Scratch (static device memory only; no allocations allowed)
// ---------------------------------------------------------------------------
__device__ __align__(256) float          g_Y[(size_t)MTOT * NTOT];        // 192 MB
__device__ __align__(256) unsigned short g_Xhi[(size_t)MTOT * HIDDEN];    // 32 MB
__device__ __align__(256) unsigned short g_Xlo[(size_t)MTOT * HIDDEN];    // 32 MB
__device__ __align__(256) unsigned short g_Whi[(size_t)NTOT * HIDDEN];    // 6 MB
__device__ __align__(256) unsigned short g_Wlo[(size_t)NTOT * HIDDEN];    // 6 MB
__device__ __align__(256) float          g_cmax[BATCH * HIDDEN * NCH];    // 1 MB

// ---------------------------------------------------------------------------
// Small helpers
// ---------------------------------------------------------------------------
__device__ __forceinline__ uint32_t smem_to_u32(const void* smem_ptr) {
    uint32_t addr;
    asm("{ .reg .u64 tmp; cvta.to.shared.u64 tmp, %1; cvt.u32.u64 %0, tmp; }"
        : "=r"(addr) : "l"(smem_ptr));
    return addr;
}

__device__ __forceinline__ void cp_async16(uint32_t saddr, const void* gaddr) {
    asm volatile("cp.async.cg.shared.global [%0], [%1], 16;"
                 :: "r"(saddr), "l"(gaddr));
}
__device__ __forceinline__ void cp_commit() {
    asm volatile("cp.async.commit_group;");
}
template <int N>
__device__ __forceinline__ void cp_wait() {
    asm volatile("cp.async.wait_group %0;" :: "n"(N));
}

__device__ __forceinline__ void ldmatrix_x4(uint32_t& r0, uint32_t& r1,
                                            uint32_t& r2, uint32_t& r3,
                                            uint32_t addr) {
    asm volatile("ldmatrix.sync.aligned.m8n8.x4.shared.b16 {%0,%1,%2,%3}, [%4];"
                 : "=r"(r0), "=r"(r1), "=r"(r2), "=r"(r3) : "r"(addr));
}

__device__ __forceinline__ void mma_bf16(float* d, const uint32_t* a,
                                         const uint32_t* b) {
    asm volatile(
        "mma.sync.aligned.m16n8k16.row.col.f32.bf16.bf16.f32 "
        "{%0,%1,%2,%3}, {%4,%5,%6,%7}, {%8,%9}, {%0,%1,%2,%3};"
        : "+f"(d[0]), "+f"(d[1]), "+f"(d[2]), "+f"(d[3])
        : "r"(a[0]), "r"(a[1]), "r"(a[2]), "r"(a[3]), "r"(b[0]), "r"(b[1]));
}

// bf16 hi/lo split helpers
__device__ __forceinline__ unsigned short f2bf(float f) {
    unsigned u = __float_as_uint(f);
    unsigned r = u + 0x7FFFu + ((u >> 16) & 1u);   // round-to-nearest-even
    return (unsigned short)(r >> 16);
}
__device__ __forceinline__ float bf2f(unsigned short b) {
    return __uint_as_float((unsigned)b << 16);
}
__device__ __forceinline__ void split1(float x, unsigned short& h, unsigned short& l) {
    h = f2bf(x);
    l = f2bf(x - bf2f(h));
}

// ---------------------------------------------------------------------------
// Prep kernels: bf16 hi/lo splits of X and of Wcat = [(W0+W1)/8 ; W1 ; W2]
// ---------------------------------------------------------------------------
__global__ __launch_bounds__(256) void prep_x_kernel(const float* __restrict__ X) {
    size_t i = (size_t)blockIdx.x * blockDim.x + threadIdx.x;   // vec4 index
    float4 v = reinterpret_cast<const float4*>(X)[i];
    ushort4 h, l;
    split1(v.x, h.x, l.x); split1(v.y, h.y, l.y);
    split1(v.z, h.z, l.z); split1(v.w, h.w, l.w);
    reinterpret_cast<ushort4*>(g_Xhi)[i] = h;
    reinterpret_cast<ushort4*>(g_Xlo)[i] = l;
}

__global__ __launch_bounds__(256) void prep_w_kernel(const float* __restrict__ W0,
                                                     const float* __restrict__ W1,
                                                     const float* __restrict__ W2) {
    size_t i = (size_t)blockIdx.x * blockDim.x + threadIdx.x;   // vec4 index
    size_t e = i * 4;
    int n = (int)(e >> 10);
    float4 w;
    if (n < HIDDEN) {
        float4 a = *reinterpret_cast<const float4*>(W0 + e);
        float4 b = *reinterpret_cast<const float4*>(W1 + e);
        w = make_float4((a.x + b.x) * 0.125f, (a.y + b.y) * 0.125f,
                        (a.z + b.z) * 0.125f, (a.w + b.w) * 0.125f);
    } else if (n < 2 * HIDDEN) {
        w = *reinterpret_cast<const float4*>(W1 + (e - (size_t)HIDDEN * HIDDEN));
    } else {
        w = *reinterpret_cast<const float4*>(W2 + (e - (size_t)2 * HIDDEN * HIDDEN));
    }
    ushort4 h, l;
    split1(w.x, h.x, l.x); split1(w.y, h.y, l.y);
    split1(w.z, h.z, l.z); split1(w.w, h.w, l.w);
    reinterpret_cast<ushort4*>(g_Whi)[i] = h;
    reinterpret_cast<ushort4*>(g_Wlo)[i] = l;
}

// ---------------------------------------------------------------------------
// GEMM: Y[16384,3072] += Xhi@Whi^T + Xhi@Wlo^T + Xlo@Whi^T  (fp32 accum)
// CTA tile 128x128, BK=64, 3-stage cp.async pipeline, mma.sync bf16.
// ---------------------------------------------------------------------------
struct KTile {
    const unsigned short* Ag;
    const unsigned short* Bg;
    int k0;
};

__device__ __forceinline__ KTile kt_desc(int kt) {
    KTile d;
    int prod = kt >> 4;            // 0: hi*hi, 1: hi*lo, 2: lo*hi
    d.k0   = (kt & 15) << 6;
    d.Ag   = (prod < 2)  ? g_Xhi : g_Xlo;
    d.Bg   = (prod == 1) ? g_Wlo : g_Whi;
    return d;
}

// Issue cp.async for one stage: A tile 128x64 bf16 + B tile 128x64 bf16,
// SW128 swizzle: phys = row*128 + ((chunk ^ (row&7))<<4)
__device__ __forceinline__ void load_stage(uint32_t sA, uint32_t sB,
                                           const KTile& d, int m0, int n0, int tid) {
#pragma unroll
    for (int i = 0; i < 4; i++) {
        int id  = tid + i * 256;
        int row = id >> 3;
        int c   = id & 7;
        uint32_t off = (uint32_t)(row << 7) | (uint32_t)(((c ^ (row & 7)) << 4));
        cp_async16(sA + off, d.Ag + ((size_t)(m0 + row) << 10) + d.k0 + c * 8);
        cp_async16(sB + off, d.Bg + ((size_t)(n0 + row) << 10) + d.k0 + c * 8);
    }
    cp_commit();
}

__global__ __launch_bounds__(256, 2) void gemm_kernel() {
    extern __shared__ char smem[];
    const uint32_t smem_base = smem_to_u32(smem);
    const int tid = threadIdx.x;
    const int wid = tid >> 5;
    const int lid = tid & 31;
    const int n0 = blockIdx.x * BN;
    const int m0 = blockIdx.y * BM;

    // Warp layout: 2 (m) x 4 (n); warp tile 64 x 32
    const int wm = (wid & 1) * 64;
    const int wn = (wid >> 1) * 32;

    // ldmatrix lane geometry (same formula for A and B x4 loads)
    const int lrow = (lid & 7) + ((lid >> 3) & 1) * 8;   // row within 16-row tile
    const int lchk = (lid >> 4);                          // 0 or 1 (k 16B chunk)

    float acc[4][4][4];
#pragma unroll
    for (int mt = 0; mt < 4; mt++)
#pragma unroll
        for (int nt = 0; nt < 4; nt++)
#pragma unroll
            for (int j = 0; j < 4; j++) acc[mt][nt][j] = 0.0f;

    // Prologue: stages 0,1
    load_stage(smem_base, smem_base + 16384, kt_desc(0), m0, n0, tid);
    load_stage(smem_base + STAGE_BYTES, smem_base + STAGE_BYTES + 16384,
               kt_desc(1), m0, n0, tid);

#pragma unroll 1
    for (int kt = 0; kt < NKT; kt++) {
        if (kt + 2 < NKT) {
            int buf = (kt + 2) % NSTAGE;
            uint32_t sb = smem_base + buf * STAGE_BYTES;
            load_stage(sb, sb + 16384, kt_desc(kt + 2), m0, n0, tid);
        }
        if (kt < NKT - 2)       cp_wait<2>();
        else if (kt == NKT - 2) cp_wait<1>();
        else                    cp_wait<0>();
        __syncthreads();

        const uint32_t sA = smem_base + (kt % NSTAGE) * STAGE_BYTES;
        const uint32_t sB = sA + 16384;

#pragma unroll
        for (int s = 0; s < 4; s++) {        // 4 sub-steps of k16
            const int chunk = 2 * s + lchk;
            // A fragments: 4 m-tiles of 16 rows
            uint32_t a[4][4];
#pragma unroll
            for (int mt = 0; mt < 4; mt++) {
                int row = wm + mt * 16 + lrow;
                uint32_t addr = sA + (uint32_t)(row << 7)
                              + (uint32_t)(((chunk ^ (row & 7)) << 4));
                ldmatrix_x4(a[mt][0], a[mt][1], a[mt][2], a[mt][3], addr);
            }
            // B fragments: 4 n-tiles of 8 rows, loaded pairwise via x4
            uint32_t b[4][2];
#pragma unroll
            for (int np = 0; np < 2; np++) {
                int row = wn + np * 16 + lrow;
                uint32_t addr = sB + (uint32_t)(row << 7)
                              + (uint32_t)(((chunk ^ (row & 7)) << 4));
                uint32_t r0, r1, r2, r3;
                ldmatrix_x4(r0, r1, r2, r3, addr);
                b[2 * np][0] = r0; b[2 * np][1] = r2;       // n rows 0-7
                b[2 * np + 1][0] = r1; b[2 * np + 1][1] = r3; // n rows 8-15
            }
#pragma unroll
            for (int mt = 0; mt < 4; mt++)
#pragma unroll
                for (int nt = 0; nt < 4; nt++)
                    mma_bf16(acc[mt][nt], a[mt], b[nt]);
        }
        __syncthreads();
    }

    // Epilogue: direct fp32 stores to g_Y
    const int r0l = lid >> 2;          // 0..7
    const int c0l = (lid & 3) * 2;     // 0,2,4,6
#pragma unroll
    for (int mt = 0; mt < 4; mt++) {
#pragma unroll
        for (int nt = 0; nt < 4; nt++) {
            size_t row = (size_t)(m0 + wm + mt * 16 + r0l);
            size_t col = (size_t)(n0 + wn + nt * 8 + c0l);
            float2* p0 = reinterpret_cast<float2*>(g_Y + row * NTOT + col);
            float2* p1 = reinterpret_cast<float2*>(g_Y + (row + 8) * NTOT + col);
            *p0 = make_float2(acc[mt][nt][0], acc[mt][nt][1]);
            *p1 = make_float2(acc[mt][nt][2], acc[mt][nt][3]);
        }
    }
}

// ---------------------------------------------------------------------------
// Scan phase 1: per-(b,channel,chunk) max of S over its CHUNK seq positions
// ---------------------------------------------------------------------------
__global__ __launch_bounds__(1024) void chunkmax_kernel() {
    const int c  = threadIdx.x;
    const int b  = blockIdx.x;
    const int ch = blockIdx.y;
    size_t base = ((size_t)(b * SEQ + ch * CHUNK)) * NTOT + c;
    float m = __int_as_float(0xff800000);   // -inf
#pragma unroll 8
    for (int s = 0; s < CHUNK; s++) {
        m = fmaxf(m, g_Y[base + (size_t)s * NTOT]);
    }
    g_cmax[(b * HIDDEN + c) * NCH + ch] = m;
}

// ---------------------------------------------------------------------------
// Scan phase 2: prefix over earlier chunks, then in-chunk cummax + epilogue
// out = (cm + out2) * cm + out1
// ---------------------------------------------------------------------------
__global__ __launch_bounds__(1024) void finalize_kernel(float* __restrict__ out) {
    const int c  = threadIdx.x;
    const int b  = blockIdx.x;
    const int ch = blockIdx.y;
    float run = __int_as_float(0xff800000);
    const float* cm = &g_cmax[(b * HIDDEN + c) * NCH];
#pragma unroll 1
    for (int j = 0; j < ch; j++) run = fmaxf(run, cm[j]);
    const size_t row0 = (size_t)b * SEQ + (size_t)ch * CHUNK;
#pragma unroll 4
    for (int s = 0; s < CHUNK; s++) {
        const size_t row = row0 + s;
        const size_t yb  = row * NTOT;
        float sv = g_Y[yb + c];
        run = fmaxf(run, sv);
        float o1 = g_Y[yb + HIDDEN + c];
        float o2 = g_Y[yb + 2 * HIDDEN + c];
        out[row * HIDDEN + c] = (run + o2) * run + o1;
    }
}

// ---------------------------------------------------------------------------
// Launch
// ---------------------------------------------------------------------------
extern "C" void kernel_launch(void* const* d_in, const int* in_sizes, int n_in,
                              void* d_out, int out_size) {
    const float* X  = (const float*)d_in[0];
    const float* W0 = (const float*)d_in[1];
    const float* W1 = (const float*)d_in[2];
    const float* W2 = (const float*)d_in[3];
    float* out = (float*)d_out;

    cudaFuncSetAttribute(gemm_kernel,
                         cudaFuncAttributeMaxDynamicSharedMemorySize, SMEM_TOTAL);

    prep_w_kernel<<<(NTOT * HIDDEN / 4) / 256, 256>>>(W0, W1, W2);
    prep_x_kernel<<<(int)(((size_t)MTOT * HIDDEN / 4) / 256), 256>>>(X);
    gemm_kernel<<<dim3(NTOT / BN, MTOT / BM), 256, SMEM_TOTAL>>>();
    chunkmax_kernel<<<dim3(BATCH, NCH), 1024>>>();
    finalize_kernel<<<dim3(BATCH, NCH), 1024>>>(out);
}

// round 4
// speedup vs baseline: 1.4198x; 1.4198x over previous
#include <cuda_runtime.h>
#include <cuda_fp16.h>
#include <cstdint>

// ---------------------------------------------------------------------------
// Problem constants
// ---------------------------------------------------------------------------
#define BATCH   4
#define SEQ     4096
#define HIDDEN  1024
#define MTOT    (BATCH * SEQ)          // 16384
#define NTOT    (3 * HIDDEN)           // 3072 (S | out1 | out2)

// GEMM tiling: CTA 128x128, BK=64, two fp16 A-operands (hi/lo) share one B
#define BM 128
#define BN 128
#define BK 64                           // 64 fp16 = 128 B row (SW128 swizzle)
#define NKT (HIDDEN / BK)               // 16 k-tiles (each does 2 products)

#define TILE_BYTES  16384               // 128 x 64 fp16
#define STAGE_BYTES (3 * TILE_BYTES)    // Ahi + Alo + B = 48 KB
#define NSTAGE 2
#define SMEM_TOTAL  (NSTAGE * STAGE_BYTES)   // 96 KB

// Scan tiling
#define NCH   64
#define CHUNK 64

// ---------------------------------------------------------------------------
// Scratch (static device memory only; no allocations allowed)
// ---------------------------------------------------------------------------
__device__ __align__(256) float          g_Y[(size_t)MTOT * NTOT];        // 192 MB
__device__ __align__(256) unsigned short g_Xhi[(size_t)MTOT * HIDDEN];    // 32 MB
__device__ __align__(256) unsigned short g_Xlo[(size_t)MTOT * HIDDEN];    // 32 MB
__device__ __align__(256) unsigned short g_Wh[(size_t)NTOT * HIDDEN];     // 6 MB
__device__ __align__(256) float          g_cmax[BATCH * HIDDEN * NCH];    // 1 MB

// ---------------------------------------------------------------------------
// Small helpers
// ---------------------------------------------------------------------------
__device__ __forceinline__ uint32_t smem_to_u32(const void* smem_ptr) {
    uint32_t addr;
    asm("{ .reg .u64 tmp; cvta.to.shared.u64 tmp, %1; cvt.u32.u64 %0, tmp; }"
        : "=r"(addr) : "l"(smem_ptr));
    return addr;
}

__device__ __forceinline__ void cp_async16(uint32_t saddr, const void* gaddr) {
    asm volatile("cp.async.cg.shared.global [%0], [%1], 16;"
                 :: "r"(saddr), "l"(gaddr));
}
__device__ __forceinline__ void cp_commit() {
    asm volatile("cp.async.commit_group;");
}
template <int N>
__device__ __forceinline__ void cp_wait() {
    asm volatile("cp.async.wait_group %0;" :: "n"(N));
}

__device__ __forceinline__ void ldmatrix_x4(uint32_t& r0, uint32_t& r1,
                                            uint32_t& r2, uint32_t& r3,
                                            uint32_t addr) {
    asm volatile("ldmatrix.sync.aligned.m8n8.x4.shared.b16 {%0,%1,%2,%3}, [%4];"
                 : "=r"(r0), "=r"(r1), "=r"(r2), "=r"(r3) : "r"(addr));
}

__device__ __forceinline__ void mma_f16(float* d, const uint32_t* a,
                                        const uint32_t* b) {
    asm volatile(
        "mma.sync.aligned.m16n8k16.row.col.f32.f16.f16.f32 "
        "{%0,%1,%2,%3}, {%4,%5,%6,%7}, {%8,%9}, {%0,%1,%2,%3};"
        : "+f"(d[0]), "+f"(d[1]), "+f"(d[2]), "+f"(d[3])
        : "r"(a[0]), "r"(a[1]), "r"(a[2]), "r"(a[3]), "r"(b[0]), "r"(b[1]));
}

// ---------------------------------------------------------------------------
// Prep kernels: fp16 hi/lo split of X; fp16 of Wcat = [(W0+W1)/8 ; W1 ; W2]
// ---------------------------------------------------------------------------
__device__ __forceinline__ void split_h(float x, unsigned short& h, unsigned short& l) {
    __half hh = __float2half_rn(x);
    __half ll = __float2half_rn(x - __half2float(hh));
    h = __half_as_ushort(hh);
    l = __half_as_ushort(ll);
}

__global__ __launch_bounds__(256) void prep_x_kernel(const float* __restrict__ X) {
    size_t i = (size_t)blockIdx.x * blockDim.x + threadIdx.x;   // vec4 index
    float4 v = reinterpret_cast<const float4*>(X)[i];
    ushort4 h, l;
    split_h(v.x, h.x, l.x); split_h(v.y, h.y, l.y);
    split_h(v.z, h.z, l.z); split_h(v.w, h.w, l.w);
    reinterpret_cast<ushort4*>(g_Xhi)[i] = h;
    reinterpret_cast<ushort4*>(g_Xlo)[i] = l;
}

__global__ __launch_bounds__(256) void prep_w_kernel(const float* __restrict__ W0,
                                                     const float* __restrict__ W1,
                                                     const float* __restrict__ W2) {
    size_t i = (size_t)blockIdx.x * blockDim.x + threadIdx.x;   // vec4 index
    size_t e = i * 4;
    int n = (int)(e >> 10);
    float4 w;
    if (n < HIDDEN) {
        float4 a = *reinterpret_cast<const float4*>(W0 + e);
        float4 b = *reinterpret_cast<const float4*>(W1 + e);
        w = make_float4((a.x + b.x) * 0.125f, (a.y + b.y) * 0.125f,
                        (a.z + b.z) * 0.125f, (a.w + b.w) * 0.125f);
    } else if (n < 2 * HIDDEN) {
        w = *reinterpret_cast<const float4*>(W1 + (e - (size_t)HIDDEN * HIDDEN));
    } else {
        w = *reinterpret_cast<const float4*>(W2 + (e - (size_t)2 * HIDDEN * HIDDEN));
    }
    ushort4 h;
    h.x = __half_as_ushort(__float2half_rn(w.x));
    h.y = __half_as_ushort(__float2half_rn(w.y));
    h.z = __half_as_ushort(__float2half_rn(w.z));
    h.w = __half_as_ushort(__float2half_rn(w.w));
    reinterpret_cast<ushort4*>(g_Wh)[i] = h;
}

// ---------------------------------------------------------------------------
// GEMM: Y[16384,3072] = Xhi@Wh^T + Xlo@Wh^T  (fp16 in, fp32 accum)
// Stage = {Ahi 16K, Alo 16K, B 16K}; 2-stage cp.async pipeline.
// ---------------------------------------------------------------------------
__device__ __forceinline__ void load_stage(uint32_t sbuf, int kt,
                                           int m0, int n0, int tid) {
    const int k0 = kt << 6;
    // Each tile: 128 rows x 8 16B-chunks = 1024 cp.asyncs; 3 tiles; 256 thr
#pragma unroll
    for (int i = 0; i < 4; i++) {
        int id  = tid + i * 256;
        int row = id >> 3;
        int c   = id & 7;
        uint32_t off = (uint32_t)(row << 7) | (uint32_t)((c ^ (row & 7)) << 4);
        cp_async16(sbuf + off,
                   g_Xhi + ((size_t)(m0 + row) << 10) + k0 + c * 8);
        cp_async16(sbuf + TILE_BYTES + off,
                   g_Xlo + ((size_t)(m0 + row) << 10) + k0 + c * 8);
        cp_async16(sbuf + 2 * TILE_BYTES + off,
                   g_Wh  + ((size_t)(n0 + row) << 10) + k0 + c * 8);
    }
    cp_commit();
}

__global__ __launch_bounds__(256, 2) void gemm_kernel() {
    extern __shared__ char smem[];
    const uint32_t smem_base = smem_to_u32(smem);
    const int tid = threadIdx.x;
    const int wid = tid >> 5;
    const int lid = tid & 31;
    const int n0 = blockIdx.x * BN;
    const int m0 = blockIdx.y * BM;

    // Warp layout: 2 (m) x 4 (n); warp tile 64 x 32
    const int wm = (wid & 1) * 64;
    const int wn = (wid >> 1) * 32;

    // ldmatrix lane geometry
    const int lrow = (lid & 7) + ((lid >> 3) & 1) * 8;   // row within 16-row tile
    const int lchk = (lid >> 4);                          // 0/1: k 16B chunk

    float acc[4][4][4];
#pragma unroll
    for (int mt = 0; mt < 4; mt++)
#pragma unroll
        for (int nt = 0; nt < 4; nt++)
#pragma unroll
            for (int j = 0; j < 4; j++) acc[mt][nt][j] = 0.0f;

    load_stage(smem_base, 0, m0, n0, tid);
    load_stage(smem_base + STAGE_BYTES, 1, m0, n0, tid);

#pragma unroll 1
    for (int kt = 0; kt < NKT; kt++) {
        if (kt < NKT - 2) cp_wait<1>();
        else              cp_wait<0>();
        __syncthreads();

        const uint32_t sbuf = smem_base + (kt & 1) * STAGE_BYTES;
        const uint32_t sB   = sbuf + 2 * TILE_BYTES;

#pragma unroll
        for (int s = 0; s < 4; s++) {        // 4 sub-steps of k16
            const int chunk = 2 * s + lchk;
            // B fragments: 4 n-tiles of 8 rows (loaded once, used twice)
            uint32_t b[4][2];
#pragma unroll
            for (int np = 0; np < 2; np++) {
                int row = wn + np * 16 + lrow;
                uint32_t addr = sB + (uint32_t)(row << 7)
                              + (uint32_t)((chunk ^ (row & 7)) << 4);
                uint32_t r0, r1, r2, r3;
                ldmatrix_x4(r0, r1, r2, r3, addr);
                b[2 * np][0] = r0;     b[2 * np][1] = r2;
                b[2 * np + 1][0] = r1; b[2 * np + 1][1] = r3;
            }
            // Product 0: A = Xhi, Product 1: A = Xlo (same accumulators)
#pragma unroll
            for (int p = 0; p < 2; p++) {
                const uint32_t sA = sbuf + p * TILE_BYTES;
                uint32_t a[4][4];
#pragma unroll
                for (int mt = 0; mt < 4; mt++) {
                    int row = wm + mt * 16 + lrow;
                    uint32_t addr = sA + (uint32_t)(row << 7)
                                  + (uint32_t)((chunk ^ (row & 7)) << 4);
                    ldmatrix_x4(a[mt][0], a[mt][1], a[mt][2], a[mt][3], addr);
                }
#pragma unroll
                for (int mt = 0; mt < 4; mt++)
#pragma unroll
                    for (int nt = 0; nt < 4; nt++)
                        mma_f16(acc[mt][nt], a[mt], b[nt]);
            }
        }
        __syncthreads();
        if (kt + 2 < NKT) {
            load_stage(smem_base + (kt & 1) * STAGE_BYTES, kt + 2, m0, n0, tid);
        }
    }

    // Epilogue: direct fp32 stores to g_Y
    const int r0l = lid >> 2;          // 0..7
    const int c0l = (lid & 3) * 2;     // 0,2,4,6
#pragma unroll
    for (int mt = 0; mt < 4; mt++) {
#pragma unroll
        for (int nt = 0; nt < 4; nt++) {
            size_t row = (size_t)(m0 + wm + mt * 16 + r0l);
            size_t col = (size_t)(n0 + wn + nt * 8 + c0l);
            float2* p0 = reinterpret_cast<float2*>(g_Y + row * NTOT + col);
            float2* p1 = reinterpret_cast<float2*>(g_Y + (row + 8) * NTOT + col);
            *p0 = make_float2(acc[mt][nt][0], acc[mt][nt][1]);
            *p1 = make_float2(acc[mt][nt][2], acc[mt][nt][3]);
        }
    }
}

// ---------------------------------------------------------------------------
// Scan phase 1: per-(b,channel,chunk) max of S over its CHUNK seq positions
// ---------------------------------------------------------------------------
__global__ __launch_bounds__(1024) void chunkmax_kernel() {
    const int c  = threadIdx.x;
    const int b  = blockIdx.x;
    const int ch = blockIdx.y;
    size_t base = ((size_t)(b * SEQ + ch * CHUNK)) * NTOT + c;
    float m = __int_as_float(0xff800000);   // -inf
#pragma unroll 8
    for (int s = 0; s < CHUNK; s++) {
        m = fmaxf(m, g_Y[base + (size_t)s * NTOT]);
    }
    g_cmax[(b * HIDDEN + c) * NCH + ch] = m;
}

// ---------------------------------------------------------------------------
// Scan phase 2: prefix over earlier chunks, then in-chunk cummax + epilogue
// out = (cm + out2) * cm + out1
// ---------------------------------------------------------------------------
__global__ __launch_bounds__(1024) void finalize_kernel(float* __restrict__ out) {
    const int c  = threadIdx.x;
    const int b  = blockIdx.x;
    const int ch = blockIdx.y;
    float run = __int_as_float(0xff800000);
    const float* cm = &g_cmax[(b * HIDDEN + c) * NCH];
#pragma unroll 1
    for (int j = 0; j < ch; j++) run = fmaxf(run, cm[j]);
    const size_t row0 = (size_t)b * SEQ + (size_t)ch * CHUNK;
#pragma unroll 4
    for (int s = 0; s < CHUNK; s++) {
        const size_t row = row0 + s;
        const size_t yb  = row * NTOT;
        float sv = g_Y[yb + c];
        run = fmaxf(run, sv);
        float o1 = g_Y[yb + HIDDEN + c];
        float o2 = g_Y[yb + 2 * HIDDEN + c];
        out[row * HIDDEN + c] = (run + o2) * run + o1;
    }
}

// ---------------------------------------------------------------------------
// Launch
// ---------------------------------------------------------------------------
extern "C" void kernel_launch(void* const* d_in, const int* in_sizes, int n_in,
                              void* d_out, int out_size) {
    const float* X  = (const float*)d_in[0];
    const float* W0 = (const float*)d_in[1];
    const float* W1 = (const float*)d_in[2];
    const float* W2 = (const float*)d_in[3];
    float* out = (float*)d_out;

    cudaFuncSetAttribute(gemm_kernel,
                         cudaFuncAttributeMaxDynamicSharedMemorySize, SMEM_TOTAL);

    prep_w_kernel<<<(NTOT * HIDDEN / 4) / 256, 256>>>(W0, W1, W2);
    prep_x_kernel<<<(int)(((size_t)MTOT * HIDDEN / 4) / 256), 256>>>(X);
    gemm_kernel<<<dim3(NTOT / BN, MTOT / BM), 256, SMEM_TOTAL>>>();
    chunkmax_kernel<<<dim3(BATCH, NCH), 1024>>>();
    finalize_kernel<<<dim3(BATCH, NCH), 1024>>>(out);
}

// round 5
// speedup vs baseline: 2.3434x; 1.6505x over previous
#include <cuda_runtime.h>
#include <cuda_fp16.h>
#include <cstdint>

// ---------------------------------------------------------------------------
// Problem constants
// ---------------------------------------------------------------------------
#define BATCH   4
#define SEQ     4096
#define HIDDEN  1024
#define MTOT    (BATCH * SEQ)          // 16384
#define NTOT    (3 * HIDDEN)           // 3072 (S | out1 | out2)

// GEMM tiling: CTA 128x128, BK=64, single-pass fp16
#define BM 128
#define BN 128
#define BK 64                           // 64 fp16 = 128 B row (SW128 swizzle)
#define NKT (HIDDEN / BK)               // 16 k-tiles

#define TILE_BYTES  16384               // 128 x 64 fp16
#define STAGE_BYTES (2 * TILE_BYTES)    // A + B = 32 KB
#define NSTAGE 3
#define SMEM_TOTAL  (NSTAGE * STAGE_BYTES)   // 96 KB

// Scan tiling
#define NCH   64
#define CHUNK 64

// ---------------------------------------------------------------------------
// Scratch (static device memory only; no allocations allowed)
// ---------------------------------------------------------------------------
__device__ __align__(256) float          g_Y[(size_t)MTOT * NTOT];        // 192 MB
__device__ __align__(256) unsigned short g_Xh[(size_t)MTOT * HIDDEN];     // 32 MB
__device__ __align__(256) unsigned short g_Wh[(size_t)NTOT * HIDDEN];     // 6 MB
__device__ __align__(256) float          g_cmax[BATCH * HIDDEN * NCH];    // 1 MB

// ---------------------------------------------------------------------------
// Small helpers
// ---------------------------------------------------------------------------
__device__ __forceinline__ uint32_t smem_to_u32(const void* smem_ptr) {
    uint32_t addr;
    asm("{ .reg .u64 tmp; cvta.to.shared.u64 tmp, %1; cvt.u32.u64 %0, tmp; }"
        : "=r"(addr) : "l"(smem_ptr));
    return addr;
}

__device__ __forceinline__ void cp_async16(uint32_t saddr, const void* gaddr) {
    asm volatile("cp.async.cg.shared.global [%0], [%1], 16;"
                 :: "r"(saddr), "l"(gaddr));
}
__device__ __forceinline__ void cp_commit() {
    asm volatile("cp.async.commit_group;");
}
template <int N>
__device__ __forceinline__ void cp_wait() {
    asm volatile("cp.async.wait_group %0;" :: "n"(N));
}

__device__ __forceinline__ void ldmatrix_x4(uint32_t& r0, uint32_t& r1,
                                            uint32_t& r2, uint32_t& r3,
                                            uint32_t addr) {
    asm volatile("ldmatrix.sync.aligned.m8n8.x4.shared.b16 {%0,%1,%2,%3}, [%4];"
                 : "=r"(r0), "=r"(r1), "=r"(r2), "=r"(r3) : "r"(addr));
}

__device__ __forceinline__ void mma_f16(float* d, const uint32_t* a,
                                        const uint32_t* b) {
    asm volatile(
        "mma.sync.aligned.m16n8k16.row.col.f32.f16.f16.f32 "
        "{%0,%1,%2,%3}, {%4,%5,%6,%7}, {%8,%9}, {%0,%1,%2,%3};"
        : "+f"(d[0]), "+f"(d[1]), "+f"(d[2]), "+f"(d[3])
        : "r"(a[0]), "r"(a[1]), "r"(a[2]), "r"(a[3]), "r"(b[0]), "r"(b[1]));
}

// ---------------------------------------------------------------------------
// Prep kernels: fp16 of X; fp16 of Wcat = [(W0+W1)/8 ; W1 ; W2]
// ---------------------------------------------------------------------------
__global__ __launch_bounds__(256) void prep_x_kernel(const float* __restrict__ X) {
    size_t i = (size_t)blockIdx.x * blockDim.x + threadIdx.x;   // vec4 index
    float4 v = reinterpret_cast<const float4*>(X)[i];
    ushort4 h;
    h.x = __half_as_ushort(__float2half_rn(v.x));
    h.y = __half_as_ushort(__float2half_rn(v.y));
    h.z = __half_as_ushort(__float2half_rn(v.z));
    h.w = __half_as_ushort(__float2half_rn(v.w));
    reinterpret_cast<ushort4*>(g_Xh)[i] = h;
}

__global__ __launch_bounds__(256) void prep_w_kernel(const float* __restrict__ W0,
                                                     const float* __restrict__ W1,
                                                     const float* __restrict__ W2) {
    size_t i = (size_t)blockIdx.x * blockDim.x + threadIdx.x;   // vec4 index
    size_t e = i * 4;
    int n = (int)(e >> 10);
    float4 w;
    if (n < HIDDEN) {
        float4 a = *reinterpret_cast<const float4*>(W0 + e);
        float4 b = *reinterpret_cast<const float4*>(W1 + e);
        w = make_float4((a.x + b.x) * 0.125f, (a.y + b.y) * 0.125f,
                        (a.z + b.z) * 0.125f, (a.w + b.w) * 0.125f);
    } else if (n < 2 * HIDDEN) {
        w = *reinterpret_cast<const float4*>(W1 + (e - (size_t)HIDDEN * HIDDEN));
    } else {
        w = *reinterpret_cast<const float4*>(W2 + (e - (size_t)2 * HIDDEN * HIDDEN));
    }
    ushort4 h;
    h.x = __half_as_ushort(__float2half_rn(w.x));
    h.y = __half_as_ushort(__float2half_rn(w.y));
    h.z = __half_as_ushort(__float2half_rn(w.z));
    h.w = __half_as_ushort(__float2half_rn(w.w));
    reinterpret_cast<ushort4*>(g_Wh)[i] = h;
}

// ---------------------------------------------------------------------------
// GEMM: Y[16384,3072] = Xh@Wh^T  (fp16 in, fp32 accum)
// Stage = {A 16K, B 16K}; 3-stage cp.async pipeline.
// ---------------------------------------------------------------------------
__device__ __forceinline__ void load_stage(uint32_t sbuf, int kt,
                                           int m0, int n0, int tid) {
    const int k0 = kt << 6;
#pragma unroll
    for (int i = 0; i < 4; i++) {
        int id  = tid + i * 256;
        int row = id >> 3;
        int c   = id & 7;
        uint32_t off = (uint32_t)(row << 7) | (uint32_t)((c ^ (row & 7)) << 4);
        cp_async16(sbuf + off,
                   g_Xh + ((size_t)(m0 + row) << 10) + k0 + c * 8);
        cp_async16(sbuf + TILE_BYTES + off,
                   g_Wh + ((size_t)(n0 + row) << 10) + k0 + c * 8);
    }
    cp_commit();
}

__global__ __launch_bounds__(256, 2) void gemm_kernel() {
    extern __shared__ char smem[];
    const uint32_t smem_base = smem_to_u32(smem);
    const int tid = threadIdx.x;
    const int wid = tid >> 5;
    const int lid = tid & 31;
    const int n0 = blockIdx.x * BN;
    const int m0 = blockIdx.y * BM;

    // Warp layout: 2 (m) x 4 (n); warp tile 64 x 32
    const int wm = (wid & 1) * 64;
    const int wn = (wid >> 1) * 32;

    // ldmatrix lane geometry
    const int lrow = (lid & 7) + ((lid >> 3) & 1) * 8;   // row within 16-row tile
    const int lchk = (lid >> 4);                          // 0/1: k 16B chunk

    float acc[4][4][4];
#pragma unroll
    for (int mt = 0; mt < 4; mt++)
#pragma unroll
        for (int nt = 0; nt < 4; nt++)
#pragma unroll
            for (int j = 0; j < 4; j++) acc[mt][nt][j] = 0.0f;

    load_stage(smem_base, 0, m0, n0, tid);
    load_stage(smem_base + STAGE_BYTES, 1, m0, n0, tid);

#pragma unroll 1
    for (int kt = 0; kt < NKT; kt++) {
        if (kt + 2 < NKT) {
            uint32_t sb = smem_base + ((kt + 2) % NSTAGE) * STAGE_BYTES;
            load_stage(sb, kt + 2, m0, n0, tid);
        }
        if (kt < NKT - 2)       cp_wait<2>();
        else if (kt == NKT - 2) cp_wait<1>();
        else                    cp_wait<0>();
        __syncthreads();

        const uint32_t sA = smem_base + (kt % NSTAGE) * STAGE_BYTES;
        const uint32_t sB = sA + TILE_BYTES;

#pragma unroll
        for (int s = 0; s < 4; s++) {        // 4 sub-steps of k16
            const int chunk = 2 * s + lchk;
            // B fragments: 4 n-tiles of 8 rows
            uint32_t b[4][2];
#pragma unroll
            for (int np = 0; np < 2; np++) {
                int row = wn + np * 16 + lrow;
                uint32_t addr = sB + (uint32_t)(row << 7)
                              + (uint32_t)((chunk ^ (row & 7)) << 4);
                uint32_t r0, r1, r2, r3;
                ldmatrix_x4(r0, r1, r2, r3, addr);
                b[2 * np][0] = r0;     b[2 * np][1] = r2;
                b[2 * np + 1][0] = r1; b[2 * np + 1][1] = r3;
            }
            // A fragments: 4 m-tiles of 16 rows
            uint32_t a[4][4];
#pragma unroll
            for (int mt = 0; mt < 4; mt++) {
                int row = wm + mt * 16 + lrow;
                uint32_t addr = sA + (uint32_t)(row << 7)
                              + (uint32_t)((chunk ^ (row & 7)) << 4);
                ldmatrix_x4(a[mt][0], a[mt][1], a[mt][2], a[mt][3], addr);
            }
#pragma unroll
            for (int mt = 0; mt < 4; mt++)
#pragma unroll
                for (int nt = 0; nt < 4; nt++)
                    mma_f16(acc[mt][nt], a[mt], b[nt]);
        }
        __syncthreads();
    }

    // Epilogue: direct fp32 stores to g_Y
    const int r0l = lid >> 2;          // 0..7
    const int c0l = (lid & 3) * 2;     // 0,2,4,6
#pragma unroll
    for (int mt = 0; mt < 4; mt++) {
#pragma unroll
        for (int nt = 0; nt < 4; nt++) {
            size_t row = (size_t)(m0 + wm + mt * 16 + r0l);
            size_t col = (size_t)(n0 + wn + nt * 8 + c0l);
            float2* p0 = reinterpret_cast<float2*>(g_Y + row * NTOT + col);
            float2* p1 = reinterpret_cast<float2*>(g_Y + (row + 8) * NTOT + col);
            *p0 = make_float2(acc[mt][nt][0], acc[mt][nt][1]);
            *p1 = make_float2(acc[mt][nt][2], acc[mt][nt][3]);
        }
    }
}

// ---------------------------------------------------------------------------
// Scan phase 1: per-(b,channel,chunk) max of S over its CHUNK seq positions
// ---------------------------------------------------------------------------
__global__ __launch_bounds__(1024) void chunkmax_kernel() {
    const int c  = threadIdx.x;
    const int b  = blockIdx.x;
    const int ch = blockIdx.y;
    size_t base = ((size_t)(b * SEQ + ch * CHUNK)) * NTOT + c;
    float m = __int_as_float(0xff800000);   // -inf
#pragma unroll 8
    for (int s = 0; s < CHUNK; s++) {
        m = fmaxf(m, g_Y[base + (size_t)s * NTOT]);
    }
    g_cmax[(b * HIDDEN + c) * NCH + ch] = m;
}

// ---------------------------------------------------------------------------
// Scan phase 2: prefix over earlier chunks, then in-chunk cummax + epilogue
// out = (cm + out2) * cm + out1
// ---------------------------------------------------------------------------
__global__ __launch_bounds__(1024) void finalize_kernel(float* __restrict__ out) {
    const int c  = threadIdx.x;
    const int b  = blockIdx.x;
    const int ch = blockIdx.y;
    float run = __int_as_float(0xff800000);
    const float* cm = &g_cmax[(b * HIDDEN + c) * NCH];
#pragma unroll 1
    for (int j = 0; j < ch; j++) run = fmaxf(run, cm[j]);
    const size_t row0 = (size_t)b * SEQ + (size_t)ch * CHUNK;
#pragma unroll 4
    for (int s = 0; s < CHUNK; s++) {
        const size_t row = row0 + s;
        const size_t yb  = row * NTOT;
        float sv = g_Y[yb + c];
        run = fmaxf(run, sv);
        float o1 = g_Y[yb + HIDDEN + c];
        float o2 = g_Y[yb + 2 * HIDDEN + c];
        out[row * HIDDEN + c] = (run + o2) * run + o1;
    }
}

// ---------------------------------------------------------------------------
// Launch
// ---------------------------------------------------------------------------
extern "C" void kernel_launch(void* const* d_in, const int* in_sizes, int n_in,
                              void* d_out, int out_size) {
    const float* X  = (const float*)d_in[0];
    const float* W0 = (const float*)d_in[1];
    const float* W1 = (const float*)d_in[2];
    const float* W2 = (const float*)d_in[3];
    float* out = (float*)d_out;

    cudaFuncSetAttribute(gemm_kernel,
                         cudaFuncAttributeMaxDynamicSharedMemorySize, SMEM_TOTAL);

    prep_w_kernel<<<(NTOT * HIDDEN / 4) / 256, 256>>>(W0, W1, W2);
    prep_x_kernel<<<(int)(((size_t)MTOT * HIDDEN / 4) / 256), 256>>>(X);
    gemm_kernel<<<dim3(NTOT / BN, MTOT / BM), 256, SMEM_TOTAL>>>();
    chunkmax_kernel<<<dim3(BATCH, NCH), 1024>>>();
    finalize_kernel<<<dim3(BATCH, NCH), 1024>>>(out);
}

// round 6
// speedup vs baseline: 2.4130x; 1.0297x over previous
#include <cuda_runtime.h>
#include <cuda_fp16.h>
#include <cstdint>

// ---------------------------------------------------------------------------
// Problem constants
// ---------------------------------------------------------------------------
#define BATCH   4
#define SEQ     4096
#define HIDDEN  1024
#define MTOT    (BATCH * SEQ)          // 16384
#define NTOT    (3 * HIDDEN)           // 3072 (S | out1 | out2)

// GEMM tiling: CTA 128x128, BK=64, single-pass fp16
#define BM 128
#define BN 128
#define BK 64                           // 64 fp16 = 128 B row (SW128 swizzle)
#define NKT (HIDDEN / BK)               // 16 k-tiles

#define TILE_BYTES  16384               // 128 x 64 fp16
#define STAGE_BYTES (2 * TILE_BYTES)    // A + B = 32 KB
#define NSTAGE 3
#define SMEM_TOTAL  (NSTAGE * STAGE_BYTES)   // 96 KB

// Scan tiling
#define NCH   64
#define CHUNK 64

// ---------------------------------------------------------------------------
// Scratch (static device memory only; no allocations allowed)
// ---------------------------------------------------------------------------
__device__ __align__(256) __half         g_Yh[(size_t)MTOT * NTOT];       // 96 MB
__device__ __align__(256) unsigned short g_Xh[(size_t)MTOT * HIDDEN];     // 32 MB
__device__ __align__(256) unsigned short g_Wh[(size_t)NTOT * HIDDEN];     // 6 MB
__device__ __align__(256) float          g_cmax[BATCH * HIDDEN * NCH];    // 1 MB

// ---------------------------------------------------------------------------
// Small helpers
// ---------------------------------------------------------------------------
__device__ __forceinline__ uint32_t smem_to_u32(const void* smem_ptr) {
    uint32_t addr;
    asm("{ .reg .u64 tmp; cvta.to.shared.u64 tmp, %1; cvt.u32.u64 %0, tmp; }"
        : "=r"(addr) : "l"(smem_ptr));
    return addr;
}

__device__ __forceinline__ void cp_async16(uint32_t saddr, const void* gaddr) {
    asm volatile("cp.async.cg.shared.global [%0], [%1], 16;"
                 :: "r"(saddr), "l"(gaddr));
}
__device__ __forceinline__ void cp_commit() {
    asm volatile("cp.async.commit_group;");
}
template <int N>
__device__ __forceinline__ void cp_wait() {
    asm volatile("cp.async.wait_group %0;" :: "n"(N));
}

__device__ __forceinline__ void ldmatrix_x4(uint32_t& r0, uint32_t& r1,
                                            uint32_t& r2, uint32_t& r3,
                                            uint32_t addr) {
    asm volatile("ldmatrix.sync.aligned.m8n8.x4.shared.b16 {%0,%1,%2,%3}, [%4];"
                 : "=r"(r0), "=r"(r1), "=r"(r2), "=r"(r3) : "r"(addr));
}

__device__ __forceinline__ void mma_f16(float* d, const uint32_t* a,
                                        const uint32_t* b) {
    asm volatile(
        "mma.sync.aligned.m16n8k16.row.col.f32.f16.f16.f32 "
        "{%0,%1,%2,%3}, {%4,%5,%6,%7}, {%8,%9}, {%0,%1,%2,%3};"
        : "+f"(d[0]), "+f"(d[1]), "+f"(d[2]), "+f"(d[3])
        : "r"(a[0]), "r"(a[1]), "r"(a[2]), "r"(a[3]), "r"(b[0]), "r"(b[1]));
}

// ---------------------------------------------------------------------------
// Prep kernels: fp16 of X; fp16 of Wcat = [(W0+W1)/8 ; W1 ; W2]
// ---------------------------------------------------------------------------
__global__ __launch_bounds__(256) void prep_x_kernel(const float* __restrict__ X) {
    size_t i = (size_t)blockIdx.x * blockDim.x + threadIdx.x;   // vec4 index
    float4 v = reinterpret_cast<const float4*>(X)[i];
    ushort4 h;
    h.x = __half_as_ushort(__float2half_rn(v.x));
    h.y = __half_as_ushort(__float2half_rn(v.y));
    h.z = __half_as_ushort(__float2half_rn(v.z));
    h.w = __half_as_ushort(__float2half_rn(v.w));
    reinterpret_cast<ushort4*>(g_Xh)[i] = h;
}

__global__ __launch_bounds__(256) void prep_w_kernel(const float* __restrict__ W0,
                                                     const float* __restrict__ W1,
                                                     const float* __restrict__ W2) {
    size_t i = (size_t)blockIdx.x * blockDim.x + threadIdx.x;   // vec4 index
    size_t e = i * 4;
    int n = (int)(e >> 10);
    float4 w;
    if (n < HIDDEN) {
        float4 a = *reinterpret_cast<const float4*>(W0 + e);
        float4 b = *reinterpret_cast<const float4*>(W1 + e);
        w = make_float4((a.x + b.x) * 0.125f, (a.y + b.y) * 0.125f,
                        (a.z + b.z) * 0.125f, (a.w + b.w) * 0.125f);
    } else if (n < 2 * HIDDEN) {
        w = *reinterpret_cast<const float4*>(W1 + (e - (size_t)HIDDEN * HIDDEN));
    } else {
        w = *reinterpret_cast<const float4*>(W2 + (e - (size_t)2 * HIDDEN * HIDDEN));
    }
    ushort4 h;
    h.x = __half_as_ushort(__float2half_rn(w.x));
    h.y = __half_as_ushort(__float2half_rn(w.y));
    h.z = __half_as_ushort(__float2half_rn(w.z));
    h.w = __half_as_ushort(__float2half_rn(w.w));
    reinterpret_cast<ushort4*>(g_Wh)[i] = h;
}

// ---------------------------------------------------------------------------
// GEMM: Yh[16384,3072] = fp16( Xh@Wh^T )  (fp16 in, fp32 accum, fp16 out)
// Stage = {A 16K, B 16K}; 3-stage cp.async pipeline; ONE sync per k-iter.
// ---------------------------------------------------------------------------
__device__ __forceinline__ void load_stage(uint32_t sbuf, int kt,
                                           int m0, int n0, int tid) {
    const int k0 = kt << 6;
#pragma unroll
    for (int i = 0; i < 4; i++) {
        int id  = tid + i * 256;
        int row = id >> 3;
        int c   = id & 7;
        uint32_t off = (uint32_t)(row << 7) | (uint32_t)((c ^ (row & 7)) << 4);
        cp_async16(sbuf + off,
                   g_Xh + ((size_t)(m0 + row) << 10) + k0 + c * 8);
        cp_async16(sbuf + TILE_BYTES + off,
                   g_Wh + ((size_t)(n0 + row) << 10) + k0 + c * 8);
    }
    cp_commit();
}

__global__ __launch_bounds__(256, 2) void gemm_kernel() {
    extern __shared__ char smem[];
    const uint32_t smem_base = smem_to_u32(smem);
    const int tid = threadIdx.x;
    const int wid = tid >> 5;
    const int lid = tid & 31;
    const int n0 = blockIdx.x * BN;
    const int m0 = blockIdx.y * BM;

    // Warp layout: 2 (m) x 4 (n); warp tile 64 x 32
    const int wm = (wid & 1) * 64;
    const int wn = (wid >> 1) * 32;

    // ldmatrix lane geometry
    const int lrow = (lid & 7) + ((lid >> 3) & 1) * 8;   // row within 16-row tile
    const int lchk = (lid >> 4);                          // 0/1: k 16B chunk

    float acc[4][4][4];
#pragma unroll
    for (int mt = 0; mt < 4; mt++)
#pragma unroll
        for (int nt = 0; nt < 4; nt++)
#pragma unroll
            for (int j = 0; j < 4; j++) acc[mt][nt][j] = 0.0f;

    load_stage(smem_base, 0, m0, n0, tid);
    load_stage(smem_base + STAGE_BYTES, 1, m0, n0, tid);

#pragma unroll 1
    for (int kt = 0; kt < NKT; kt++) {
        if (kt == NKT - 1) cp_wait<0>();
        else               cp_wait<1>();
        __syncthreads();
        // Prefetch kt+2: its buffer ((kt+2)%3 == (kt-1)%3) was last read in
        // iteration kt-1, which every warp finished before the barrier above.
        if (kt + 2 < NKT) {
            uint32_t sb = smem_base + ((kt + 2) % NSTAGE) * STAGE_BYTES;
            load_stage(sb, kt + 2, m0, n0, tid);
        }

        const uint32_t sA = smem_base + (kt % NSTAGE) * STAGE_BYTES;
        const uint32_t sB = sA + TILE_BYTES;

#pragma unroll
        for (int s = 0; s < 4; s++) {        // 4 sub-steps of k16
            const int chunk = 2 * s + lchk;
            // B fragments: 4 n-tiles of 8 rows
            uint32_t b[4][2];
#pragma unroll
            for (int np = 0; np < 2; np++) {
                int row = wn + np * 16 + lrow;
                uint32_t addr = sB + (uint32_t)(row << 7)
                              + (uint32_t)((chunk ^ (row & 7)) << 4);
                uint32_t r0, r1, r2, r3;
                ldmatrix_x4(r0, r1, r2, r3, addr);
                b[2 * np][0] = r0;     b[2 * np][1] = r2;
                b[2 * np + 1][0] = r1; b[2 * np + 1][1] = r3;
            }
            // A fragments: 4 m-tiles of 16 rows
            uint32_t a[4][4];
#pragma unroll
            for (int mt = 0; mt < 4; mt++) {
                int row = wm + mt * 16 + lrow;
                uint32_t addr = sA + (uint32_t)(row << 7)
                              + (uint32_t)((chunk ^ (row & 7)) << 4);
                ldmatrix_x4(a[mt][0], a[mt][1], a[mt][2], a[mt][3], addr);
            }
#pragma unroll
            for (int mt = 0; mt < 4; mt++)
#pragma unroll
                for (int nt = 0; nt < 4; nt++)
                    mma_f16(acc[mt][nt], a[mt], b[nt]);
        }
    }

    // Epilogue: fp16 stores to g_Yh (half2 per row-pair fragment)
    const int r0l = lid >> 2;          // 0..7
    const int c0l = (lid & 3) * 2;     // 0,2,4,6
#pragma unroll
    for (int mt = 0; mt < 4; mt++) {
#pragma unroll
        for (int nt = 0; nt < 4; nt++) {
            size_t row = (size_t)(m0 + wm + mt * 16 + r0l);
            size_t col = (size_t)(n0 + wn + nt * 8 + c0l);
            __half2 h0 = __floats2half2_rn(acc[mt][nt][0], acc[mt][nt][1]);
            __half2 h1 = __floats2half2_rn(acc[mt][nt][2], acc[mt][nt][3]);
            *reinterpret_cast<__half2*>(g_Yh + row * NTOT + col) = h0;
            *reinterpret_cast<__half2*>(g_Yh + (row + 8) * NTOT + col) = h1;
        }
    }
}

// ---------------------------------------------------------------------------
// Scan phase 1: per-(b,channel,chunk) max of S over its CHUNK seq positions
// 512 threads; each handles 2 adjacent channels via half2.
// ---------------------------------------------------------------------------
__global__ __launch_bounds__(512) void chunkmax_kernel() {
    const int c  = threadIdx.x * 2;
    const int b  = blockIdx.x;
    const int ch = blockIdx.y;
    size_t base = ((size_t)(b * SEQ + ch * CHUNK)) * NTOT + c;
    float m0 = __int_as_float(0xff800000);
    float m1 = m0;
#pragma unroll 8
    for (int s = 0; s < CHUNK; s++) {
        __half2 v = *reinterpret_cast<const __half2*>(g_Yh + base + (size_t)s * NTOT);
        float2 f = __half22float2(v);
        m0 = fmaxf(m0, f.x);
        m1 = fmaxf(m1, f.y);
    }
    g_cmax[(b * HIDDEN + c) * NCH + ch]     = m0;
    g_cmax[(b * HIDDEN + c + 1) * NCH + ch] = m1;
}

// ---------------------------------------------------------------------------
// Scan phase 2: prefix over earlier chunks, then in-chunk cummax + epilogue
// out = (cm + out2) * cm + out1   (512 threads, 2 channels each)
// ---------------------------------------------------------------------------
__global__ __launch_bounds__(512) void finalize_kernel(float* __restrict__ out) {
    const int c  = threadIdx.x * 2;
    const int b  = blockIdx.x;
    const int ch = blockIdx.y;
    float run0 = __int_as_float(0xff800000);
    float run1 = run0;
    const float* cm0 = &g_cmax[(b * HIDDEN + c) * NCH];
    const float* cm1 = &g_cmax[(b * HIDDEN + c + 1) * NCH];
#pragma unroll 1
    for (int j = 0; j < ch; j++) {
        run0 = fmaxf(run0, cm0[j]);
        run1 = fmaxf(run1, cm1[j]);
    }
    const size_t row0 = (size_t)b * SEQ + (size_t)ch * CHUNK;
#pragma unroll 4
    for (int s = 0; s < CHUNK; s++) {
        const size_t row = row0 + s;
        const size_t yb  = row * NTOT;
        float2 sv = __half22float2(*reinterpret_cast<const __half2*>(g_Yh + yb + c));
        run0 = fmaxf(run0, sv.x);
        run1 = fmaxf(run1, sv.y);
        float2 o1 = __half22float2(*reinterpret_cast<const __half2*>(g_Yh + yb + HIDDEN + c));
        float2 o2 = __half22float2(*reinterpret_cast<const __half2*>(g_Yh + yb + 2 * HIDDEN + c));
        float2 r;
        r.x = (run0 + o2.x) * run0 + o1.x;
        r.y = (run1 + o2.y) * run1 + o1.y;
        *reinterpret_cast<float2*>(out + row * HIDDEN + c) = r;
    }
}

// ---------------------------------------------------------------------------
// Launch
// ---------------------------------------------------------------------------
extern "C" void kernel_launch(void* const* d_in, const int* in_sizes, int n_in,
                              void* d_out, int out_size) {
    const float* X  = (const float*)d_in[0];
    const float* W0 = (const float*)d_in[1];
    const float* W1 = (const float*)d_in[2];
    const float* W2 = (const float*)d_in[3];
    float* out = (float*)d_out;

    cudaFuncSetAttribute(gemm_kernel,
                         cudaFuncAttributeMaxDynamicSharedMemorySize, SMEM_TOTAL);

    prep_w_kernel<<<(NTOT * HIDDEN / 4) / 256, 256>>>(W0, W1, W2);
    prep_x_kernel<<<(int)(((size_t)MTOT * HIDDEN / 4) / 256), 256>>>(X);
    gemm_kernel<<<dim3(NTOT / BN, MTOT / BM), 256, SMEM_TOTAL>>>();
    chunkmax_kernel<<<dim3(BATCH, NCH), 512>>>();
    finalize_kernel<<<dim3(BATCH, NCH), 512>>>(out);
}

// round 7
// speedup vs baseline: 2.6841x; 1.1123x over previous
#include <cuda_runtime.h>
#include <cuda_fp16.h>
#include <cstdint>

// ---------------------------------------------------------------------------
// Problem constants
// ---------------------------------------------------------------------------
#define BATCH   4
#define SEQ     4096
#define HIDDEN  1024
#define MTOT    (BATCH * SEQ)          // 16384
#define NTOT    (3 * HIDDEN)           // 3072 (S | out1 | out2)

// GEMM tiling: CTA 128x128, BK=64, single-pass fp16
#define BM 128
#define BN 128
#define BK 64                           // 64 fp16 = 128 B row (SW128 swizzle)
#define NKT (HIDDEN / BK)               // 16 k-tiles

#define TILE_BYTES  16384               // 128 x 64 fp16
#define STAGE_BYTES (2 * TILE_BYTES)    // A + B = 32 KB
#define NSTAGE 3
#define SMEM_TOTAL  (NSTAGE * STAGE_BYTES)   // 96 KB

// Scan tiling: 32-row chunks
#define NCH   128
#define CHUNK 32

// ---------------------------------------------------------------------------
// Scratch (static device memory only; no allocations allowed)
// ---------------------------------------------------------------------------
__device__ __align__(256) __half         g_Yh[(size_t)MTOT * NTOT];       // 96 MB
__device__ __align__(256) unsigned short g_Xh[(size_t)MTOT * HIDDEN];     // 32 MB
__device__ __align__(256) unsigned short g_Wh[(size_t)NTOT * HIDDEN];     // 6 MB
__device__ __align__(256) float          g_cmax[(size_t)BATCH * HIDDEN * NCH]; // 2 MB

// ---------------------------------------------------------------------------
// Small helpers
// ---------------------------------------------------------------------------
__device__ __forceinline__ uint32_t smem_to_u32(const void* smem_ptr) {
    uint32_t addr;
    asm("{ .reg .u64 tmp; cvta.to.shared.u64 tmp, %1; cvt.u32.u64 %0, tmp; }"
        : "=r"(addr) : "l"(smem_ptr));
    return addr;
}

__device__ __forceinline__ void cp_async16(uint32_t saddr, const void* gaddr) {
    asm volatile("cp.async.cg.shared.global [%0], [%1], 16;"
                 :: "r"(saddr), "l"(gaddr));
}
__device__ __forceinline__ void cp_commit() {
    asm volatile("cp.async.commit_group;");
}
template <int N>
__device__ __forceinline__ void cp_wait() {
    asm volatile("cp.async.wait_group %0;" :: "n"(N));
}

__device__ __forceinline__ void ldmatrix_x4(uint32_t& r0, uint32_t& r1,
                                            uint32_t& r2, uint32_t& r3,
                                            uint32_t addr) {
    asm volatile("ldmatrix.sync.aligned.m8n8.x4.shared.b16 {%0,%1,%2,%3}, [%4];"
                 : "=r"(r0), "=r"(r1), "=r"(r2), "=r"(r3) : "r"(addr));
}

__device__ __forceinline__ void mma_f16(float* d, const uint32_t* a,
                                        const uint32_t* b) {
    asm volatile(
        "mma.sync.aligned.m16n8k16.row.col.f32.f16.f16.f32 "
        "{%0,%1,%2,%3}, {%4,%5,%6,%7}, {%8,%9}, {%0,%1,%2,%3};"
        : "+f"(d[0]), "+f"(d[1]), "+f"(d[2]), "+f"(d[3])
        : "r"(a[0]), "r"(a[1]), "r"(a[2]), "r"(a[3]), "r"(b[0]), "r"(b[1]));
}

#define NEG_INF __int_as_float(0xff800000)

// ---------------------------------------------------------------------------
// Prep kernels: fp16 of X; fp16 of Wcat = [(W0+W1)/8 ; W1 ; W2]
// ---------------------------------------------------------------------------
__global__ __launch_bounds__(256) void prep_x_kernel(const float* __restrict__ X) {
    size_t i = (size_t)blockIdx.x * blockDim.x + threadIdx.x;   // vec4 index
    float4 v = reinterpret_cast<const float4*>(X)[i];
    ushort4 h;
    h.x = __half_as_ushort(__float2half_rn(v.x));
    h.y = __half_as_ushort(__float2half_rn(v.y));
    h.z = __half_as_ushort(__float2half_rn(v.z));
    h.w = __half_as_ushort(__float2half_rn(v.w));
    reinterpret_cast<ushort4*>(g_Xh)[i] = h;
}

__global__ __launch_bounds__(256) void prep_w_kernel(const float* __restrict__ W0,
                                                     const float* __restrict__ W1,
                                                     const float* __restrict__ W2) {
    size_t i = (size_t)blockIdx.x * blockDim.x + threadIdx.x;   // vec4 index
    size_t e = i * 4;
    int n = (int)(e >> 10);
    float4 w;
    if (n < HIDDEN) {
        float4 a = *reinterpret_cast<const float4*>(W0 + e);
        float4 b = *reinterpret_cast<const float4*>(W1 + e);
        w = make_float4((a.x + b.x) * 0.125f, (a.y + b.y) * 0.125f,
                        (a.z + b.z) * 0.125f, (a.w + b.w) * 0.125f);
    } else if (n < 2 * HIDDEN) {
        w = *reinterpret_cast<const float4*>(W1 + (e - (size_t)HIDDEN * HIDDEN));
    } else {
        w = *reinterpret_cast<const float4*>(W2 + (e - (size_t)2 * HIDDEN * HIDDEN));
    }
    ushort4 h;
    h.x = __half_as_ushort(__float2half_rn(w.x));
    h.y = __half_as_ushort(__float2half_rn(w.y));
    h.z = __half_as_ushort(__float2half_rn(w.z));
    h.w = __half_as_ushort(__float2half_rn(w.w));
    reinterpret_cast<ushort4*>(g_Wh)[i] = h;
}

// ---------------------------------------------------------------------------
// GEMM: Yh[16384,3072] = fp16( Xh@Wh^T ); fused per-chunk max of S columns.
// Stage = {A 16K, B 16K}; 3-stage cp.async pipeline; one sync per k-iter.
// ---------------------------------------------------------------------------
__device__ __forceinline__ void load_stage(uint32_t sbuf, int kt,
                                           int m0, int n0, int tid) {
    const int k0 = kt << 6;
#pragma unroll
    for (int i = 0; i < 4; i++) {
        int id  = tid + i * 256;
        int row = id >> 3;
        int c   = id & 7;
        uint32_t off = (uint32_t)(row << 7) | (uint32_t)((c ^ (row & 7)) << 4);
        cp_async16(sbuf + off,
                   g_Xh + ((size_t)(m0 + row) << 10) + k0 + c * 8);
        cp_async16(sbuf + TILE_BYTES + off,
                   g_Wh + ((size_t)(n0 + row) << 10) + k0 + c * 8);
    }
    cp_commit();
}

__global__ __launch_bounds__(256, 2) void gemm_kernel() {
    extern __shared__ char smem[];
    const uint32_t smem_base = smem_to_u32(smem);
    const int tid = threadIdx.x;
    const int wid = tid >> 5;
    const int lid = tid & 31;
    const int n0 = blockIdx.x * BN;
    const int m0 = blockIdx.y * BM;

    // Warp layout: 2 (m) x 4 (n); warp tile 64 x 32
    const int wm = (wid & 1) * 64;
    const int wn = (wid >> 1) * 32;

    // ldmatrix lane geometry
    const int lrow = (lid & 7) + ((lid >> 3) & 1) * 8;   // row within 16-row tile
    const int lchk = (lid >> 4);                          // 0/1: k 16B chunk

    float acc[4][4][4];
#pragma unroll
    for (int mt = 0; mt < 4; mt++)
#pragma unroll
        for (int nt = 0; nt < 4; nt++)
#pragma unroll
            for (int j = 0; j < 4; j++) acc[mt][nt][j] = 0.0f;

    load_stage(smem_base, 0, m0, n0, tid);
    load_stage(smem_base + STAGE_BYTES, 1, m0, n0, tid);

#pragma unroll 1
    for (int kt = 0; kt < NKT; kt++) {
        if (kt == NKT - 1) cp_wait<0>();
        else               cp_wait<1>();
        __syncthreads();
        // Prefetch kt+2: its buffer was last read in iteration kt-1, which
        // every warp finished before the barrier above.
        if (kt + 2 < NKT) {
            uint32_t sb = smem_base + ((kt + 2) % NSTAGE) * STAGE_BYTES;
            load_stage(sb, kt + 2, m0, n0, tid);
        }

        const uint32_t sA = smem_base + (kt % NSTAGE) * STAGE_BYTES;
        const uint32_t sB = sA + TILE_BYTES;

#pragma unroll
        for (int s = 0; s < 4; s++) {        // 4 sub-steps of k16
            const int chunk = 2 * s + lchk;
            uint32_t b[4][2];
#pragma unroll
            for (int np = 0; np < 2; np++) {
                int row = wn + np * 16 + lrow;
                uint32_t addr = sB + (uint32_t)(row << 7)
                              + (uint32_t)((chunk ^ (row & 7)) << 4);
                uint32_t r0, r1, r2, r3;
                ldmatrix_x4(r0, r1, r2, r3, addr);
                b[2 * np][0] = r0;     b[2 * np][1] = r2;
                b[2 * np + 1][0] = r1; b[2 * np + 1][1] = r3;
            }
            uint32_t a[4][4];
#pragma unroll
            for (int mt = 0; mt < 4; mt++) {
                int row = wm + mt * 16 + lrow;
                uint32_t addr = sA + (uint32_t)(row << 7)
                              + (uint32_t)((chunk ^ (row & 7)) << 4);
                ldmatrix_x4(a[mt][0], a[mt][1], a[mt][2], a[mt][3], addr);
            }
#pragma unroll
            for (int mt = 0; mt < 4; mt++)
#pragma unroll
                for (int nt = 0; nt < 4; nt++)
                    mma_f16(acc[mt][nt], a[mt], b[nt]);
        }
    }

    // Fused chunk-max for S columns (n0 < HIDDEN): warp tile covers two
    // 32-row chunks (mt 0,1 -> rows 0..31; mt 2,3 -> rows 32..63).
    if (n0 < HIDDEN) {
        const int b_idx  = m0 >> 12;                       // batch
        const int chbase = ((m0 & 4095) >> 5) + (wm >> 5); // 32-row chunk idx
#pragma unroll
        for (int half = 0; half < 2; half++) {
#pragma unroll
            for (int nt = 0; nt < 4; nt++) {
                float v0 = NEG_INF, v1 = NEG_INF;
#pragma unroll
                for (int mt = 2 * half; mt < 2 * half + 2; mt++) {
                    v0 = fmaxf(v0, fmaxf(acc[mt][nt][0], acc[mt][nt][2]));
                    v1 = fmaxf(v1, fmaxf(acc[mt][nt][1], acc[mt][nt][3]));
                }
#pragma unroll
                for (int msk = 4; msk <= 16; msk <<= 1) {
                    v0 = fmaxf(v0, __shfl_xor_sync(0xffffffffu, v0, msk));
                    v1 = fmaxf(v1, __shfl_xor_sync(0xffffffffu, v1, msk));
                }
                if (lid < 4) {
                    int col = n0 + wn + nt * 8 + lid * 2;
                    int ch  = chbase + half;
                    g_cmax[((size_t)(b_idx * HIDDEN + col)) * NCH + ch]     = v0;
                    g_cmax[((size_t)(b_idx * HIDDEN + col + 1)) * NCH + ch] = v1;
                }
            }
        }
    }

    // Epilogue: fp16 stores to g_Yh
    const int r0l = lid >> 2;          // 0..7
    const int c0l = (lid & 3) * 2;     // 0,2,4,6
#pragma unroll
    for (int mt = 0; mt < 4; mt++) {
#pragma unroll
        for (int nt = 0; nt < 4; nt++) {
            size_t row = (size_t)(m0 + wm + mt * 16 + r0l);
            size_t col = (size_t)(n0 + wn + nt * 8 + c0l);
            __half2 h0 = __floats2half2_rn(acc[mt][nt][0], acc[mt][nt][1]);
            __half2 h1 = __floats2half2_rn(acc[mt][nt][2], acc[mt][nt][3]);
            *reinterpret_cast<__half2*>(g_Yh + row * NTOT + col) = h0;
            *reinterpret_cast<__half2*>(g_Yh + (row + 8) * NTOT + col) = h1;
        }
    }
}

// ---------------------------------------------------------------------------
// Prefix kernel: in-place convert g_cmax rows into EXCLUSIVE prefix maxes.
// One block of 128 threads per (b, channel).
// ---------------------------------------------------------------------------
__global__ __launch_bounds__(128) void prefix_kernel() {
    __shared__ float s[NCH];
    const int tid = threadIdx.x;
    float* row = g_cmax + (size_t)blockIdx.x * NCH;
    float v = row[tid];
    s[tid] = v;
    __syncthreads();
#pragma unroll
    for (int off = 1; off < NCH; off <<= 1) {
        float t = (tid >= off) ? s[tid - off] : NEG_INF;
        __syncthreads();
        s[tid] = fmaxf(s[tid], t);
        __syncthreads();
    }
    float excl = (tid == 0) ? NEG_INF : s[tid - 1];
    row[tid] = excl;
}

// ---------------------------------------------------------------------------
// Finalize: run = prefix[ch]; in-chunk (32-row) cummax + epilogue
// out = (cm + out2) * cm + out1   (512 threads, 2 channels each)
// ---------------------------------------------------------------------------
__global__ __launch_bounds__(512) void finalize_kernel(float* __restrict__ out) {
    const int c  = threadIdx.x * 2;
    const int b  = blockIdx.x;
    const int ch = blockIdx.y;
    float run0 = g_cmax[((size_t)(b * HIDDEN + c)) * NCH + ch];
    float run1 = g_cmax[((size_t)(b * HIDDEN + c + 1)) * NCH + ch];
    const size_t row0 = (size_t)b * SEQ + (size_t)ch * CHUNK;
#pragma unroll 4
    for (int s = 0; s < CHUNK; s++) {
        const size_t row = row0 + s;
        const size_t yb  = row * NTOT;
        float2 sv = __half22float2(*reinterpret_cast<const __half2*>(g_Yh + yb + c));
        run0 = fmaxf(run0, sv.x);
        run1 = fmaxf(run1, sv.y);
        float2 o1 = __half22float2(*reinterpret_cast<const __half2*>(g_Yh + yb + HIDDEN + c));
        float2 o2 = __half22float2(*reinterpret_cast<const __half2*>(g_Yh + yb + 2 * HIDDEN + c));
        float2 r;
        r.x = (run0 + o2.x) * run0 + o1.x;
        r.y = (run1 + o2.y) * run1 + o1.y;
        *reinterpret_cast<float2*>(out + row * HIDDEN + c) = r;
    }
}

// ---------------------------------------------------------------------------
// Launch
// ---------------------------------------------------------------------------
extern "C" void kernel_launch(void* const* d_in, const int* in_sizes, int n_in,
                              void* d_out, int out_size) {
    const float* X  = (const float*)d_in[0];
    const float* W0 = (const float*)d_in[1];
    const float* W1 = (const float*)d_in[2];
    const float* W2 = (const float*)d_in[3];
    float* out = (float*)d_out;

    cudaFuncSetAttribute(gemm_kernel,
                         cudaFuncAttributeMaxDynamicSharedMemorySize, SMEM_TOTAL);

    prep_w_kernel<<<(NTOT * HIDDEN / 4) / 256, 256>>>(W0, W1, W2);
    prep_x_kernel<<<(int)(((size_t)MTOT * HIDDEN / 4) / 256), 256>>>(X);
    gemm_kernel<<<dim3(NTOT / BN, MTOT / BM), 256, SMEM_TOTAL>>>();
    prefix_kernel<<<BATCH * HIDDEN, 128>>>();
    finalize_kernel<<<dim3(BATCH, NCH), 512>>>(out);
}